// round 16
// baseline (speedup 1.0000x reference)
#include <cuda_runtime.h>
#include <cuda_bf16.h>
#include <cstdint>

#define N_NODES 50000
#define N_EDGES 1600000
#define D       128
#define DHID    256
#define BM      32
#define TILES   ((N_NODES + BM - 1) / BM)     // 1563
#define GRID    296
#define LN_EPS  1e-5f
#define SBLK    256
#define NSB     ((N_NODES + SBLK - 1) / SBLK) // 196

// ---------------- smem layout (bytes) ----------------
// A buffers: [32 rows][264 bf16] (528B stride), hi + lo, double buffered
#define ASTR     528
#define BUF_SZ   16896                 // 32*528
#define OFF_BUF(i, pol) ((i) * 2 * BUF_SZ + (pol) * BUF_SZ)
#define OFF_WH   67584                 // [256 n][80 B] = 20480 (32-k slice)
#define OFF_WL   88064
#define OFF_B1S  108544
#define OFF_B2S  109568
#define OFF_GS   110080
#define OFF_BTS  110592
#define SMEM_TOT 111104                // x2 blocks = 222,208 <= 227KB cap

// CSR + weight scratch
__device__ int g_count[N_NODES];
__device__ int g_off[N_NODES + 1];
__device__ int g_cursor[N_NODES];
__device__ int g_eid[N_EDGES];
__device__ int g_bsum[NSB];
__device__ int g_idx_is64;
__device__ __align__(16) __nv_bfloat16 g_w1t_hi[DHID * 2 * D];  // [n=256][k=256]
__device__ __align__(16) __nv_bfloat16 g_w1t_lo[DHID * 2 * D];
__device__ __align__(16) __nv_bfloat16 g_w2t_hi[D * DHID];      // [n=128][k=256]
__device__ __align__(16) __nv_bfloat16 g_w2t_lo[D * DHID];

// ---------------- helpers ----------------
__device__ __forceinline__ uint32_t smem_u32(const void* p) {
    uint32_t a;
    asm("{ .reg .u64 t; cvta.to.shared.u64 t, %1; cvt.u32.u64 %0, t; }" : "=r"(a) : "l"(p));
    return a;
}
__device__ __forceinline__ void ldm_x4(uint32_t* r, uint32_t addr) {
    asm volatile("ldmatrix.sync.aligned.m8n8.x4.shared.b16 {%0,%1,%2,%3}, [%4];"
        : "=r"(r[0]), "=r"(r[1]), "=r"(r[2]), "=r"(r[3]) : "r"(addr));
}
__device__ __forceinline__ void ldm_x2(uint32_t* r, uint32_t addr) {
    asm volatile("ldmatrix.sync.aligned.m8n8.x2.shared.b16 {%0,%1}, [%2];"
        : "=r"(r[0]), "=r"(r[1]) : "r"(addr));
}
__device__ __forceinline__ void mma_bf16(float* d, const uint32_t* a, const uint32_t* b) {
    asm volatile("mma.sync.aligned.m16n8k16.row.col.f32.bf16.bf16.f32 "
        "{%0,%1,%2,%3}, {%4,%5,%6,%7}, {%8,%9}, {%0,%1,%2,%3};"
        : "+f"(d[0]), "+f"(d[1]), "+f"(d[2]), "+f"(d[3])
        : "r"(a[0]), "r"(a[1]), "r"(a[2]), "r"(a[3]), "r"(b[0]), "r"(b[1]));
}
__device__ __forceinline__ void split2(float a, float b, uint32_t& hi, uint32_t& lo) {
    __nv_bfloat162 h = __float22bfloat162_rn(make_float2(a, b));
    float2 hf = __bfloat1622float2(h);
    __nv_bfloat162 l = __float22bfloat162_rn(make_float2(a - hf.x, b - hf.y));
    hi = *(uint32_t*)&h;
    lo = *(uint32_t*)&l;
}
__device__ __forceinline__ float silu(float v) { return v / (1.f + __expf(-v)); }
#define BARC() asm volatile("bar.sync 1, 256;" ::: "memory")

// ---------------------------------------------------------------------------
// CSR build + weight prep (merged launches)
// ---------------------------------------------------------------------------
__global__ void zero_detect_prep_kernel(const void* __restrict__ edge_index,
                                        const float* __restrict__ W1,
                                        const float* __restrict__ W2) {
    int i = blockIdx.x * blockDim.x + threadIdx.x;
    if (i < N_NODES) g_count[i] = 0;
    if (i == 0) {
        const long long* p64 = (const long long*)edge_index;
        int ok64 = 1;
        #pragma unroll 1
        for (int t = 0; t < 64; t++) {
            long long v = p64[t];
            if (v < 0 || v >= N_NODES) ok64 = 0;
        }
        g_idx_is64 = ok64;
    }
    if (i < 2 * D * DHID) {            // W1[k=256][n=256]
        int k = i >> 8, n = i & 255;
        float v = W1[i];
        __nv_bfloat16 h = __float2bfloat16_rn(v);
        __nv_bfloat16 l = __float2bfloat16_rn(v - __bfloat162float(h));
        g_w1t_hi[n * 256 + k] = h;
        g_w1t_lo[n * 256 + k] = l;
    }
    if (i < DHID * D) {                // W2[k=256][n=128]
        int k = i >> 7, n = i & 127;
        float v = W2[i];
        __nv_bfloat16 h = __float2bfloat16_rn(v);
        __nv_bfloat16 l = __float2bfloat16_rn(v - __bfloat162float(h));
        g_w2t_hi[n * 256 + k] = h;
        g_w2t_lo[n * 256 + k] = l;
    }
}
__device__ __forceinline__ int load_dst(const void* edge_index, int e) {
    if (g_idx_is64) return (int)((const long long*)edge_index)[N_EDGES + e];
    return ((const int*)edge_index)[N_EDGES + e];
}
__global__ void hist_kernel(const void* __restrict__ edge_index) {
    int e = blockIdx.x * blockDim.x + threadIdx.x;
    if (e < N_EDGES) atomicAdd(&g_count[load_dst(edge_index, e)], 1);
}
__global__ __launch_bounds__(SBLK) void bsum_kernel() {
    __shared__ int wsum[8];
    int i = blockIdx.x * SBLK + threadIdx.x;
    int v = (i < N_NODES) ? g_count[i] : 0;
    int s = v;
    #pragma unroll
    for (int o = 16; o > 0; o >>= 1) s += __shfl_xor_sync(0xffffffffu, s, o);
    if ((threadIdx.x & 31) == 0) wsum[threadIdx.x >> 5] = s;
    __syncthreads();
    if (threadIdx.x == 0) {
        int t = 0;
        #pragma unroll
        for (int w = 0; w < 8; w++) t += wsum[w];
        g_bsum[blockIdx.x] = t;
    }
}
// offs: inline scan of g_bsum prefix (no separate bscan kernel)
__global__ __launch_bounds__(SBLK) void offs_kernel() {
    __shared__ int wsum[8];
    __shared__ int s_bbase;
    int tid = threadIdx.x, lane = tid & 31, warp = tid >> 5;

    if (warp == 0) {
        int acc = 0;
        for (int i = lane; i < blockIdx.x; i += 32) acc += g_bsum[i];
        #pragma unroll
        for (int o = 16; o > 0; o >>= 1) acc += __shfl_xor_sync(0xffffffffu, acc, o);
        if (lane == 0) s_bbase = acc;
    }

    int i = blockIdx.x * SBLK + tid;
    int v = (i < N_NODES) ? g_count[i] : 0;
    int incl = v;
    #pragma unroll
    for (int o = 1; o < 32; o <<= 1) {
        int t = __shfl_up_sync(0xffffffffu, incl, o);
        if (lane >= o) incl += t;
    }
    if (lane == 31) wsum[warp] = incl;
    __syncthreads();
    int wbase = 0;
    #pragma unroll
    for (int w = 0; w < 8; w++) wbase += (w < warp) ? wsum[w] : 0;
    int excl = s_bbase + wbase + incl - v;
    if (i < N_NODES) { g_off[i] = excl; g_cursor[i] = excl; }
    if (blockIdx.x == 0 && tid == 0) g_off[N_NODES] = N_EDGES;
}
__global__ void fill_kernel(const void* __restrict__ edge_index) {
    int e = blockIdx.x * blockDim.x + threadIdx.x;
    if (e < N_EDGES) {
        int dst = load_dst(edge_index, e);
        int pos = atomicAdd(&g_cursor[dst], 1);
        g_eid[pos] = e;
    }
}

// ---------------------------------------------------------------------------
// persistent warp-specialized pipeline, 32-node tiles, 2 blocks/SM:
// 512 thr: warps 0-7 produce (gather tile t+1), warps 8-15 consume (GEMM tile t)
// ---------------------------------------------------------------------------
__global__ __launch_bounds__(512, 2) void fused_kernel(
    const float* __restrict__ x,
    const float* __restrict__ edge_attr,
    const float* __restrict__ b1, const float* __restrict__ b2,
    const float* __restrict__ gamma, const float* __restrict__ beta,
    float* __restrict__ out)
{
    extern __shared__ unsigned char smem_raw[];
    const uint32_t sb = smem_u32(smem_raw);
    float* b1s = (float*)(smem_raw + OFF_B1S);
    float* b2s = (float*)(smem_raw + OFF_B2S);
    float* gs  = (float*)(smem_raw + OFF_GS);
    float* bts = (float*)(smem_raw + OFF_BTS);

    const int tid  = threadIdx.x;
    const int wid  = tid >> 5;
    const int lane = tid & 31;
    const int bid  = blockIdx.x;

    if (tid < 256) b1s[tid] = b1[tid];
    if (tid < 128) { b2s[tid] = b2[tid]; gs[tid] = gamma[tid]; bts[tid] = beta[tid]; }

    const int n_it = (TILES - bid + GRID - 1) / GRID;   // tiles for this block

    for (int it = 0; it <= n_it; it++) {
        // ---------------- producers: gather tile(it) into buf[it&1] ----------
        if (wid < 8) {
            if (it < n_it) {
                const int tile  = bid + it * GRID;
                const int node0 = tile * BM;
                unsigned char* bufH = smem_raw + OFF_BUF(it & 1, 0);
                unsigned char* bufL = smem_raw + OFF_BUF(it & 1, 1);
                #pragma unroll 1
                for (int i = 0; i < 4; i++) {
                    int row  = wid * 4 + i;
                    int node = node0 + row;
                    float4 xv  = make_float4(0.f, 0.f, 0.f, 0.f);
                    float4 acc = make_float4(0.f, 0.f, 0.f, 0.f);
                    if (node < N_NODES) {
                        xv = ((const float4*)x)[(long long)node * 32 + lane];
                        int beg = g_off[node];
                        int end = g_off[node + 1];
                        for (int p = beg; p < end; p += 32) {
                            int n   = min(32, end - p);
                            int eid = (p + lane < end) ? g_eid[p + lane] : 0;
                            int j = 0;
                            for (; j + 8 <= n; j += 8) {
                                int e0 = __shfl_sync(0xffffffffu, eid, j);
                                int e1 = __shfl_sync(0xffffffffu, eid, j + 1);
                                int e2 = __shfl_sync(0xffffffffu, eid, j + 2);
                                int e3 = __shfl_sync(0xffffffffu, eid, j + 3);
                                int e4 = __shfl_sync(0xffffffffu, eid, j + 4);
                                int e5 = __shfl_sync(0xffffffffu, eid, j + 5);
                                int e6 = __shfl_sync(0xffffffffu, eid, j + 6);
                                int e7 = __shfl_sync(0xffffffffu, eid, j + 7);
                                float4 v0 = ((const float4*)edge_attr)[(long long)e0 * 32 + lane];
                                float4 v1 = ((const float4*)edge_attr)[(long long)e1 * 32 + lane];
                                float4 v2 = ((const float4*)edge_attr)[(long long)e2 * 32 + lane];
                                float4 v3 = ((const float4*)edge_attr)[(long long)e3 * 32 + lane];
                                float4 v4 = ((const float4*)edge_attr)[(long long)e4 * 32 + lane];
                                float4 v5 = ((const float4*)edge_attr)[(long long)e5 * 32 + lane];
                                float4 v6 = ((const float4*)edge_attr)[(long long)e6 * 32 + lane];
                                float4 v7 = ((const float4*)edge_attr)[(long long)e7 * 32 + lane];
                                acc.x += ((v0.x + v1.x) + (v2.x + v3.x)) + ((v4.x + v5.x) + (v6.x + v7.x));
                                acc.y += ((v0.y + v1.y) + (v2.y + v3.y)) + ((v4.y + v5.y) + (v6.y + v7.y));
                                acc.z += ((v0.z + v1.z) + (v2.z + v3.z)) + ((v4.z + v5.z) + (v6.z + v7.z));
                                acc.w += ((v0.w + v1.w) + (v2.w + v3.w)) + ((v4.w + v5.w) + (v6.w + v7.w));
                            }
                            for (; j < n; j++) {
                                int e0 = __shfl_sync(0xffffffffu, eid, j);
                                float4 v0 = ((const float4*)edge_attr)[(long long)e0 * 32 + lane];
                                acc.x += v0.x; acc.y += v0.y; acc.z += v0.z; acc.w += v0.w;
                            }
                        }
                    }
                    uint32_t hi, lo;
                    unsigned char* rH = bufH + row * ASTR;
                    unsigned char* rL = bufL + row * ASTR;
                    split2(xv.x, xv.y, hi, lo);
                    *(uint32_t*)(rH + lane * 8)     = hi;  *(uint32_t*)(rL + lane * 8)     = lo;
                    split2(xv.z, xv.w, hi, lo);
                    *(uint32_t*)(rH + lane * 8 + 4) = hi;  *(uint32_t*)(rL + lane * 8 + 4) = lo;
                    split2(acc.x, acc.y, hi, lo);
                    *(uint32_t*)(rH + 256 + lane * 8)     = hi;  *(uint32_t*)(rL + 256 + lane * 8)     = lo;
                    split2(acc.z, acc.w, hi, lo);
                    *(uint32_t*)(rH + 256 + lane * 8 + 4) = hi;  *(uint32_t*)(rL + 256 + lane * 8 + 4) = lo;
                }
            }
        }
        // ---------------- consumers: full MLP on tile(it-1) from buf[(it-1)&1]
        else {
            if (it >= 1) {
                const int tile  = bid + (it - 1) * GRID;
                const int node0 = tile * BM;
                const int b     = (it - 1) & 1;
                const uint32_t bufH = sb + OFF_BUF(b, 0);
                const int ctid = tid - 256;
                const int cw   = wid - 8;
                const int mg   = cw & 1;
                const int ng   = cw >> 1;
                const int m0   = mg * 16;
                const int jq   = 2 * (lane & 3);
                uint32_t* swh = (uint32_t*)(smem_raw + OFF_WH);   // [256 n][20 u32]
                uint32_t* swl = (uint32_t*)(smem_raw + OFF_WL);

                // ======== GEMM1: [32,256], 32-k staged ========
                float d1[8][4];
                {
                    const int n0 = ng * 64;
                    #pragma unroll
                    for (int nt = 0; nt < 8; nt++) {
                        float bx = b1s[n0 + nt * 8 + jq];
                        float by = b1s[n0 + nt * 8 + jq + 1];
                        d1[nt][0] = bx; d1[nt][1] = by; d1[nt][2] = bx; d1[nt][3] = by;
                    }
                    const uint32_t* gw1h = (const uint32_t*)g_w1t_hi;
                    const uint32_t* gw1l = (const uint32_t*)g_w1t_lo;
                    #pragma unroll 1
                    for (int kt = 0; kt < 8; kt++) {
                        BARC();
                        #pragma unroll
                        for (int it2 = 0; it2 < 16; it2++) {
                            int idx = it2 * 256 + ctid;
                            int n = idx >> 4, ku = idx & 15;
                            swh[n * 20 + ku] = gw1h[n * 128 + kt * 16 + ku];
                            swl[n * 20 + ku] = gw1l[n * 128 + kt * 16 + ku];
                        }
                        BARC();
                        #pragma unroll
                        for (int sub = 0; sub < 2; sub++) {
                            uint32_t ah[4], al[4];
                            uint32_t aaddr = bufH + (m0 + (lane & 15)) * ASTR
                                + (kt * 32 + sub * 16 + ((lane >> 4) & 1) * 8) * 2;
                            ldm_x4(ah, aaddr);
                            ldm_x4(al, aaddr + BUF_SZ);
                            #pragma unroll
                            for (int nt = 0; nt < 8; nt++) {
                                uint32_t baddr = sb + OFF_WH
                                    + (n0 + nt * 8 + (lane & 7)) * 80
                                    + (sub * 16 + ((lane >> 3) & 1) * 8) * 2;
                                uint32_t bh[2], bl[2];
                                ldm_x2(bh, baddr);
                                ldm_x2(bl, baddr + (OFF_WL - OFF_WH));
                                mma_bf16(d1[nt], ah, bh);
                                mma_bf16(d1[nt], ah, bl);
                                mma_bf16(d1[nt], al, bh);
                            }
                        }
                    }
                }
                BARC();   // all A reads done before h1 overwrites buf

                // ---- epilogue1: h1 = silu(D1) split -> same buf ----
                {
                    const int n0 = ng * 64;
                    int r0 = m0 + (lane >> 2);
                    int r1 = r0 + 8;
                    #pragma unroll
                    for (int nt = 0; nt < 8; nt++) {
                        int j0 = n0 + nt * 8 + jq;
                        float s0 = silu(d1[nt][0]);
                        float s1 = silu(d1[nt][1]);
                        float s2 = silu(d1[nt][2]);
                        float s3 = silu(d1[nt][3]);
                        uint32_t hi, lo;
                        split2(s0, s1, hi, lo);
                        *(uint32_t*)(smem_raw + OFF_BUF(b, 0) + r0 * ASTR + j0 * 2) = hi;
                        *(uint32_t*)(smem_raw + OFF_BUF(b, 1) + r0 * ASTR + j0 * 2) = lo;
                        split2(s2, s3, hi, lo);
                        *(uint32_t*)(smem_raw + OFF_BUF(b, 0) + r1 * ASTR + j0 * 2) = hi;
                        *(uint32_t*)(smem_raw + OFF_BUF(b, 1) + r1 * ASTR + j0 * 2) = lo;
                    }
                }
                BARC();

                // ======== GEMM2: [32,128], 32-k staged ========
                float d2[4][4];
                {
                    const int n0 = ng * 32;
                    #pragma unroll
                    for (int nt = 0; nt < 4; nt++) {
                        float bx = b2s[n0 + nt * 8 + jq];
                        float by = b2s[n0 + nt * 8 + jq + 1];
                        d2[nt][0] = bx; d2[nt][1] = by; d2[nt][2] = bx; d2[nt][3] = by;
                    }
                    const uint32_t* gw2h = (const uint32_t*)g_w2t_hi;
                    const uint32_t* gw2l = (const uint32_t*)g_w2t_lo;
                    #pragma unroll 1
                    for (int kt = 0; kt < 8; kt++) {
                        BARC();
                        #pragma unroll
                        for (int it2 = 0; it2 < 8; it2++) {
                            int idx = it2 * 256 + ctid;
                            int n = idx >> 4, ku = idx & 15;
                            swh[n * 20 + ku] = gw2h[n * 128 + kt * 16 + ku];
                            swl[n * 20 + ku] = gw2l[n * 128 + kt * 16 + ku];
                        }
                        BARC();
                        #pragma unroll
                        for (int sub = 0; sub < 2; sub++) {
                            uint32_t ah[4], al[4];
                            uint32_t aaddr = bufH + (m0 + (lane & 15)) * ASTR
                                + (kt * 32 + sub * 16 + ((lane >> 4) & 1) * 8) * 2;
                            ldm_x4(ah, aaddr);
                            ldm_x4(al, aaddr + BUF_SZ);
                            #pragma unroll
                            for (int nt = 0; nt < 4; nt++) {
                                uint32_t baddr = sb + OFF_WH
                                    + (n0 + nt * 8 + (lane & 7)) * 80
                                    + (sub * 16 + ((lane >> 3) & 1) * 8) * 2;
                                uint32_t bh[2], bl[2];
                                ldm_x2(bh, baddr);
                                ldm_x2(bl, baddr + (OFF_WL - OFF_WH));
                                mma_bf16(d2[nt], ah, bh);
                                mma_bf16(d2[nt], ah, bl);
                                mma_bf16(d2[nt], al, bh);
                            }
                        }
                    }
                }
                BARC();   // all h1 reads done

                // ---- epilogue2: fp32 D2 -> s_out (aliases bufL) ----
                {
                    float* so = (float*)(smem_raw + OFF_BUF(b, 1));   // [32][132]
                    const int n0 = ng * 32;
                    int r0 = m0 + (lane >> 2);
                    int r1 = r0 + 8;
                    #pragma unroll
                    for (int nt = 0; nt < 4; nt++) {
                        int j0 = n0 + nt * 8 + jq;
                        so[r0 * 132 + j0]     = d2[nt][0];
                        so[r0 * 132 + j0 + 1] = d2[nt][1];
                        so[r1 * 132 + j0]     = d2[nt][2];
                        so[r1 * 132 + j0 + 1] = d2[nt][3];
                    }
                }
                BARC();

                // ---- LayerNorm + residual: consumer warp cw -> rows cw*4..+3 ----
                {
                    const float* so = (const float*)(smem_raw + OFF_BUF(b, 1));
                    #pragma unroll 1
                    for (int rr = 0; rr < 4; rr++) {
                        int row  = cw * 4 + rr;
                        int node = node0 + row;
                        float v0 = so[row * 132 + lane];
                        float v1 = so[row * 132 + lane + 32];
                        float v2 = so[row * 132 + lane + 64];
                        float v3 = so[row * 132 + lane + 96];
                        float sum = v0 + v1 + v2 + v3;
                        float sq  = v0 * v0 + v1 * v1 + v2 * v2 + v3 * v3;
                        #pragma unroll
                        for (int o = 16; o > 0; o >>= 1) {
                            sum += __shfl_xor_sync(0xffffffffu, sum, o);
                            sq  += __shfl_xor_sync(0xffffffffu, sq,  o);
                        }
                        float mean = sum * (1.f / D);
                        float var  = sq * (1.f / D) - mean * mean;
                        float rstd = rsqrtf(var + LN_EPS);
                        if (node < N_NODES) {
                            long long base = (long long)node * D;
                            float g0 = gs[lane],      t0 = bts[lane];
                            float g1 = gs[lane + 32], t1 = bts[lane + 32];
                            float g2 = gs[lane + 64], t2 = bts[lane + 64];
                            float g3 = gs[lane + 96], t3 = bts[lane + 96];
                            out[base + lane]      = x[base + lane]      + (v0 - mean) * rstd * g0 + t0;
                            out[base + lane + 32] = x[base + lane + 32] + (v1 - mean) * rstd * g1 + t1;
                            out[base + lane + 64] = x[base + lane + 64] + (v2 - mean) * rstd * g2 + t2;
                            out[base + lane + 96] = x[base + lane + 96] + (v3 - mean) * rstd * g3 + t3;
                        }
                    }
                }
            }
        }
        __syncthreads();   // hand buffers across pipeline stages
    }
}

// ---------------------------------------------------------------------------
extern "C" void kernel_launch(void* const* d_in, const int* in_sizes, int n_in,
                              void* d_out, int out_size)
{
    const float* x          = (const float*)d_in[0];
    const void*  edge_index = d_in[1];
    const float* edge_attr  = (const float*)d_in[2];
    const float* W1         = (const float*)d_in[3];
    const float* b1         = (const float*)d_in[4];
    const float* W2         = (const float*)d_in[5];
    const float* b2         = (const float*)d_in[6];
    const float* gamma      = (const float*)d_in[7];
    const float* beta       = (const float*)d_in[8];
    float* out = (float*)d_out;

    cudaFuncSetAttribute(fused_kernel,
                         cudaFuncAttributeMaxDynamicSharedMemorySize, SMEM_TOT);

    zero_detect_prep_kernel<<<(2 * D * DHID + 255) / 256, 256>>>(edge_index, W1, W2);
    hist_kernel<<<(N_EDGES + 255) / 256, 256>>>(edge_index);
    bsum_kernel<<<NSB, SBLK>>>();
    offs_kernel<<<NSB, SBLK>>>();
    fill_kernel<<<(N_EDGES + 255) / 256, 256>>>(edge_index);

    fused_kernel<<<GRID, 512, SMEM_TOT>>>(
        x, edge_attr, b1, b2, gamma, beta, out);
}

// round 17
// speedup vs baseline: 1.1050x; 1.1050x over previous
#include <cuda_runtime.h>
#include <cuda_bf16.h>
#include <cstdint>

#define N_NODES 50000
#define N_EDGES 1600000
#define D       128
#define DHID    256
#define BM      32
#define TILES   ((N_NODES + BM - 1) / BM)     // 1563
#define GRID    148
#define LN_EPS  1e-5f
#define SBLK    256
#define NSB     ((N_NODES + SBLK - 1) / SBLK) // 196

// ---------------- smem layout (bytes) ----------------
// A buffers: [32 rows][264 bf16] (528B stride), hi + lo, double buffered
#define ASTR     528
#define BUF_SZ   16896                 // 32*528
#define OFF_BUF(i, pol) ((i) * 2 * BUF_SZ + (pol) * BUF_SZ)
#define OFF_WH   67584                 // [256 n][144 B] = 36864 (64-k slice)
#define OFF_WL   104448
#define OFF_B1S  141312
#define OFF_B2S  142336
#define OFF_GS   142848
#define OFF_BTS  143360
#define SMEM_TOT 143872

// CSR + weight scratch
__device__ int g_count[N_NODES];
__device__ int g_off[N_NODES + 1];
__device__ int g_cursor[N_NODES];
__device__ int g_eid[N_EDGES];
__device__ int g_bsum[NSB];
__device__ int g_idx_is64;
__device__ __align__(16) __nv_bfloat16 g_w1t_hi[DHID * 2 * D];  // [n=256][k=256]
__device__ __align__(16) __nv_bfloat16 g_w1t_lo[DHID * 2 * D];
__device__ __align__(16) __nv_bfloat16 g_w2t_hi[D * DHID];      // [n=128][k=256]
__device__ __align__(16) __nv_bfloat16 g_w2t_lo[D * DHID];

// ---------------- helpers ----------------
__device__ __forceinline__ uint32_t smem_u32(const void* p) {
    uint32_t a;
    asm("{ .reg .u64 t; cvta.to.shared.u64 t, %1; cvt.u32.u64 %0, t; }" : "=r"(a) : "l"(p));
    return a;
}
__device__ __forceinline__ void ldm_x4(uint32_t* r, uint32_t addr) {
    asm volatile("ldmatrix.sync.aligned.m8n8.x4.shared.b16 {%0,%1,%2,%3}, [%4];"
        : "=r"(r[0]), "=r"(r[1]), "=r"(r[2]), "=r"(r[3]) : "r"(addr));
}
__device__ __forceinline__ void ldm_x2(uint32_t* r, uint32_t addr) {
    asm volatile("ldmatrix.sync.aligned.m8n8.x2.shared.b16 {%0,%1}, [%2];"
        : "=r"(r[0]), "=r"(r[1]) : "r"(addr));
}
__device__ __forceinline__ void mma_bf16(float* d, const uint32_t* a, const uint32_t* b) {
    asm volatile("mma.sync.aligned.m16n8k16.row.col.f32.bf16.bf16.f32 "
        "{%0,%1,%2,%3}, {%4,%5,%6,%7}, {%8,%9}, {%0,%1,%2,%3};"
        : "+f"(d[0]), "+f"(d[1]), "+f"(d[2]), "+f"(d[3])
        : "r"(a[0]), "r"(a[1]), "r"(a[2]), "r"(a[3]), "r"(b[0]), "r"(b[1]));
}
__device__ __forceinline__ void split2(float a, float b, uint32_t& hi, uint32_t& lo) {
    __nv_bfloat162 h = __float22bfloat162_rn(make_float2(a, b));
    float2 hf = __bfloat1622float2(h);
    __nv_bfloat162 l = __float22bfloat162_rn(make_float2(a - hf.x, b - hf.y));
    hi = *(uint32_t*)&h;
    lo = *(uint32_t*)&l;
}
__device__ __forceinline__ float silu(float v) { return v / (1.f + __expf(-v)); }
#define BARC() asm volatile("bar.sync 1, 256;" ::: "memory")

// ---------------------------------------------------------------------------
// CSR build + weight prep (merged launches)
// ---------------------------------------------------------------------------
__global__ void zero_detect_prep_kernel(const void* __restrict__ edge_index,
                                        const float* __restrict__ W1,
                                        const float* __restrict__ W2) {
    int i = blockIdx.x * blockDim.x + threadIdx.x;
    if (i < N_NODES) g_count[i] = 0;
    if (i == 0) {
        const long long* p64 = (const long long*)edge_index;
        int ok64 = 1;
        #pragma unroll 1
        for (int t = 0; t < 64; t++) {
            long long v = p64[t];
            if (v < 0 || v >= N_NODES) ok64 = 0;
        }
        g_idx_is64 = ok64;
    }
    if (i < 2 * D * DHID) {            // W1[k=256][n=256]
        int k = i >> 8, n = i & 255;
        float v = W1[i];
        __nv_bfloat16 h = __float2bfloat16_rn(v);
        __nv_bfloat16 l = __float2bfloat16_rn(v - __bfloat162float(h));
        g_w1t_hi[n * 256 + k] = h;
        g_w1t_lo[n * 256 + k] = l;
    }
    if (i < DHID * D) {                // W2[k=256][n=128]
        int k = i >> 7, n = i & 127;
        float v = W2[i];
        __nv_bfloat16 h = __float2bfloat16_rn(v);
        __nv_bfloat16 l = __float2bfloat16_rn(v - __bfloat162float(h));
        g_w2t_hi[n * 256 + k] = h;
        g_w2t_lo[n * 256 + k] = l;
    }
}
__device__ __forceinline__ int load_dst(const void* edge_index, int e) {
    if (g_idx_is64) return (int)((const long long*)edge_index)[N_EDGES + e];
    return ((const int*)edge_index)[N_EDGES + e];
}
__global__ void hist_kernel(const void* __restrict__ edge_index) {
    int e = blockIdx.x * blockDim.x + threadIdx.x;
    if (e < N_EDGES) atomicAdd(&g_count[load_dst(edge_index, e)], 1);
}
__global__ __launch_bounds__(SBLK) void bsum_kernel() {
    __shared__ int wsum[8];
    int i = blockIdx.x * SBLK + threadIdx.x;
    int v = (i < N_NODES) ? g_count[i] : 0;
    int s = v;
    #pragma unroll
    for (int o = 16; o > 0; o >>= 1) s += __shfl_xor_sync(0xffffffffu, s, o);
    if ((threadIdx.x & 31) == 0) wsum[threadIdx.x >> 5] = s;
    __syncthreads();
    if (threadIdx.x == 0) {
        int t = 0;
        #pragma unroll
        for (int w = 0; w < 8; w++) t += wsum[w];
        g_bsum[blockIdx.x] = t;
    }
}
// offs: inline scan of g_bsum prefix (no separate bscan kernel)
__global__ __launch_bounds__(SBLK) void offs_kernel() {
    __shared__ int wsum[8];
    __shared__ int s_bbase;
    int tid = threadIdx.x, lane = tid & 31, warp = tid >> 5;

    if (warp == 0) {
        int acc = 0;
        for (int i = lane; i < blockIdx.x; i += 32) acc += g_bsum[i];
        #pragma unroll
        for (int o = 16; o > 0; o >>= 1) acc += __shfl_xor_sync(0xffffffffu, acc, o);
        if (lane == 0) s_bbase = acc;
    }

    int i = blockIdx.x * SBLK + tid;
    int v = (i < N_NODES) ? g_count[i] : 0;
    int incl = v;
    #pragma unroll
    for (int o = 1; o < 32; o <<= 1) {
        int t = __shfl_up_sync(0xffffffffu, incl, o);
        if (lane >= o) incl += t;
    }
    if (lane == 31) wsum[warp] = incl;
    __syncthreads();
    int wbase = 0;
    #pragma unroll
    for (int w = 0; w < 8; w++) wbase += (w < warp) ? wsum[w] : 0;
    int excl = s_bbase + wbase + incl - v;
    if (i < N_NODES) { g_off[i] = excl; g_cursor[i] = excl; }
    if (blockIdx.x == 0 && tid == 0) g_off[N_NODES] = N_EDGES;
}
__global__ void fill_kernel(const void* __restrict__ edge_index) {
    int e = blockIdx.x * blockDim.x + threadIdx.x;
    if (e < N_EDGES) {
        int dst = load_dst(edge_index, e);
        int pos = atomicAdd(&g_cursor[dst], 1);
        g_eid[pos] = e;
    }
}

// ---------------------------------------------------------------------------
// persistent warp-specialized pipeline, 32-node tiles, half-warp-row gather:
// 512 thr: warps 0-7 produce (2 rows concurrently per warp), warps 8-15 consume
// ---------------------------------------------------------------------------
__global__ __launch_bounds__(512, 1) void fused_kernel(
    const float* __restrict__ x,
    const float* __restrict__ edge_attr,
    const float* __restrict__ b1, const float* __restrict__ b2,
    const float* __restrict__ gamma, const float* __restrict__ beta,
    float* __restrict__ out)
{
    extern __shared__ unsigned char smem_raw[];
    const uint32_t sb = smem_u32(smem_raw);
    float* b1s = (float*)(smem_raw + OFF_B1S);
    float* b2s = (float*)(smem_raw + OFF_B2S);
    float* gs  = (float*)(smem_raw + OFF_GS);
    float* bts = (float*)(smem_raw + OFF_BTS);

    const int tid  = threadIdx.x;
    const int wid  = tid >> 5;
    const int lane = tid & 31;
    const int bid  = blockIdx.x;

    if (tid < 256) b1s[tid] = b1[tid];
    if (tid < 128) { b2s[tid] = b2[tid]; gs[tid] = gamma[tid]; bts[tid] = beta[tid]; }

    const int n_it = (TILES - bid + GRID - 1) / GRID;   // tiles for this block

    for (int it = 0; it <= n_it; it++) {
        // ---------------- producers: gather tile(it) into buf[it&1] ----------
        // Each warp handles 4 rows as 2 PAIRS; within a pair the two half-warps
        // process two rows CONCURRENTLY (16 lanes x 32B per edge row).
        if (wid < 8) {
            if (it < n_it) {
                const int tile  = bid + it * GRID;
                const int node0 = tile * BM;
                unsigned char* bufH = smem_raw + OFF_BUF(it & 1, 0);
                unsigned char* bufL = smem_raw + OFF_BUF(it & 1, 1);
                const int half = lane >> 4;           // 0 or 1
                const int hl   = lane & 15;           // half-lane
                const unsigned hmask = half ? 0xFFFF0000u : 0x0000FFFFu;
                const int srcb = half << 4;

                #pragma unroll 1
                for (int pr = 0; pr < 2; pr++) {
                    int row  = wid * 4 + pr * 2 + half;
                    int node = node0 + row;
                    float4 xv0  = make_float4(0.f, 0.f, 0.f, 0.f);
                    float4 xv1  = make_float4(0.f, 0.f, 0.f, 0.f);
                    float4 acc0 = make_float4(0.f, 0.f, 0.f, 0.f);
                    float4 acc1 = make_float4(0.f, 0.f, 0.f, 0.f);
                    if (node < N_NODES) {
                        xv0 = ((const float4*)x)[(long long)node * 32 + hl * 2];
                        xv1 = ((const float4*)x)[(long long)node * 32 + hl * 2 + 1];
                        int beg = g_off[node];
                        int end = g_off[node + 1];
                        for (int p = beg; p < end; p += 16) {
                            int n   = min(16, end - p);
                            int eid = (p + hl < end) ? g_eid[p + hl] : 0;
                            int j = 0;
                            for (; j + 4 <= n; j += 4) {
                                int e0 = __shfl_sync(hmask, eid, srcb + j);
                                int e1 = __shfl_sync(hmask, eid, srcb + j + 1);
                                int e2 = __shfl_sync(hmask, eid, srcb + j + 2);
                                int e3 = __shfl_sync(hmask, eid, srcb + j + 3);
                                float4 a0 = ((const float4*)edge_attr)[(long long)e0 * 32 + hl * 2];
                                float4 c0 = ((const float4*)edge_attr)[(long long)e0 * 32 + hl * 2 + 1];
                                float4 a1 = ((const float4*)edge_attr)[(long long)e1 * 32 + hl * 2];
                                float4 c1 = ((const float4*)edge_attr)[(long long)e1 * 32 + hl * 2 + 1];
                                float4 a2 = ((const float4*)edge_attr)[(long long)e2 * 32 + hl * 2];
                                float4 c2 = ((const float4*)edge_attr)[(long long)e2 * 32 + hl * 2 + 1];
                                float4 a3 = ((const float4*)edge_attr)[(long long)e3 * 32 + hl * 2];
                                float4 c3 = ((const float4*)edge_attr)[(long long)e3 * 32 + hl * 2 + 1];
                                acc0.x += (a0.x + a1.x) + (a2.x + a3.x);
                                acc0.y += (a0.y + a1.y) + (a2.y + a3.y);
                                acc0.z += (a0.z + a1.z) + (a2.z + a3.z);
                                acc0.w += (a0.w + a1.w) + (a2.w + a3.w);
                                acc1.x += (c0.x + c1.x) + (c2.x + c3.x);
                                acc1.y += (c0.y + c1.y) + (c2.y + c3.y);
                                acc1.z += (c0.z + c1.z) + (c2.z + c3.z);
                                acc1.w += (c0.w + c1.w) + (c2.w + c3.w);
                            }
                            for (; j < n; j++) {
                                int e0 = __shfl_sync(hmask, eid, srcb + j);
                                float4 a0 = ((const float4*)edge_attr)[(long long)e0 * 32 + hl * 2];
                                float4 c0 = ((const float4*)edge_attr)[(long long)e0 * 32 + hl * 2 + 1];
                                acc0.x += a0.x; acc0.y += a0.y; acc0.z += a0.z; acc0.w += a0.w;
                                acc1.x += c0.x; acc1.y += c0.y; acc1.z += c0.z; acc1.w += c0.w;
                            }
                        }
                    }
                    uint32_t hi, lo;
                    unsigned char* rH = bufH + row * ASTR;
                    unsigned char* rL = bufL + row * ASTR;
                    // x half: quads hl*2, hl*2+1 -> bytes hl*16 .. hl*16+15
                    split2(xv0.x, xv0.y, hi, lo);
                    *(uint32_t*)(rH + hl * 16)      = hi;  *(uint32_t*)(rL + hl * 16)      = lo;
                    split2(xv0.z, xv0.w, hi, lo);
                    *(uint32_t*)(rH + hl * 16 + 4)  = hi;  *(uint32_t*)(rL + hl * 16 + 4)  = lo;
                    split2(xv1.x, xv1.y, hi, lo);
                    *(uint32_t*)(rH + hl * 16 + 8)  = hi;  *(uint32_t*)(rL + hl * 16 + 8)  = lo;
                    split2(xv1.z, xv1.w, hi, lo);
                    *(uint32_t*)(rH + hl * 16 + 12) = hi;  *(uint32_t*)(rL + hl * 16 + 12) = lo;
                    // agg half at +256B
                    split2(acc0.x, acc0.y, hi, lo);
                    *(uint32_t*)(rH + 256 + hl * 16)      = hi;  *(uint32_t*)(rL + 256 + hl * 16)      = lo;
                    split2(acc0.z, acc0.w, hi, lo);
                    *(uint32_t*)(rH + 256 + hl * 16 + 4)  = hi;  *(uint32_t*)(rL + 256 + hl * 16 + 4)  = lo;
                    split2(acc1.x, acc1.y, hi, lo);
                    *(uint32_t*)(rH + 256 + hl * 16 + 8)  = hi;  *(uint32_t*)(rL + 256 + hl * 16 + 8)  = lo;
                    split2(acc1.z, acc1.w, hi, lo);
                    *(uint32_t*)(rH + 256 + hl * 16 + 12) = hi;  *(uint32_t*)(rL + 256 + hl * 16 + 12) = lo;
                }
            }
        }
        // ---------------- consumers: full MLP on tile(it-1) from buf[(it-1)&1]
        else {
            if (it >= 1) {
                const int tile  = bid + (it - 1) * GRID;
                const int node0 = tile * BM;
                const int b     = (it - 1) & 1;
                const uint32_t bufH = sb + OFF_BUF(b, 0);
                const int ctid = tid - 256;
                const int cw   = wid - 8;
                const int mg   = cw & 1;
                const int ng   = cw >> 1;
                const int m0   = mg * 16;
                const int jq   = 2 * (lane & 3);
                uint32_t* swh = (uint32_t*)(smem_raw + OFF_WH);   // [256 n][36 u32]
                uint32_t* swl = (uint32_t*)(smem_raw + OFF_WL);

                // ======== GEMM1: [32,256], k staged in 64-slices ========
                float d1[8][4];
                {
                    const int n0 = ng * 64;
                    #pragma unroll
                    for (int nt = 0; nt < 8; nt++) {
                        float bx = b1s[n0 + nt * 8 + jq];
                        float by = b1s[n0 + nt * 8 + jq + 1];
                        d1[nt][0] = bx; d1[nt][1] = by; d1[nt][2] = bx; d1[nt][3] = by;
                    }
                    const uint32_t* gw1h = (const uint32_t*)g_w1t_hi;
                    const uint32_t* gw1l = (const uint32_t*)g_w1t_lo;
                    #pragma unroll 1
                    for (int kt = 0; kt < 4; kt++) {
                        BARC();
                        #pragma unroll
                        for (int it2 = 0; it2 < 32; it2++) {
                            int idx = it2 * 256 + ctid;   // 8192 u32
                            int n = idx >> 5, ku = idx & 31;
                            swh[n * 36 + ku] = gw1h[n * 128 + kt * 32 + ku];
                            swl[n * 36 + ku] = gw1l[n * 128 + kt * 32 + ku];
                        }
                        BARC();
                        #pragma unroll
                        for (int sub = 0; sub < 4; sub++) {
                            uint32_t ah[4], al[4];
                            uint32_t aaddr = bufH + (m0 + (lane & 15)) * ASTR
                                + (kt * 64 + sub * 16 + ((lane >> 4) & 1) * 8) * 2;
                            ldm_x4(ah, aaddr);
                            ldm_x4(al, aaddr + BUF_SZ);
                            #pragma unroll
                            for (int nt = 0; nt < 8; nt++) {
                                uint32_t baddr = sb + OFF_WH
                                    + (n0 + nt * 8 + (lane & 7)) * 144
                                    + (sub * 16 + ((lane >> 3) & 1) * 8) * 2;
                                uint32_t bh[2], bl[2];
                                ldm_x2(bh, baddr);
                                ldm_x2(bl, baddr + (OFF_WL - OFF_WH));
                                mma_bf16(d1[nt], ah, bh);
                                mma_bf16(d1[nt], ah, bl);
                                mma_bf16(d1[nt], al, bh);
                            }
                        }
                    }
                }
                BARC();   // all A reads done before h1 overwrites buf

                // ---- epilogue1: h1 = silu(D1) split -> same buf ----
                {
                    const int n0 = ng * 64;
                    int r0 = m0 + (lane >> 2);
                    int r1 = r0 + 8;
                    #pragma unroll
                    for (int nt = 0; nt < 8; nt++) {
                        int j0 = n0 + nt * 8 + jq;
                        float s0 = silu(d1[nt][0]);
                        float s1 = silu(d1[nt][1]);
                        float s2 = silu(d1[nt][2]);
                        float s3 = silu(d1[nt][3]);
                        uint32_t hi, lo;
                        split2(s0, s1, hi, lo);
                        *(uint32_t*)(smem_raw + OFF_BUF(b, 0) + r0 * ASTR + j0 * 2) = hi;
                        *(uint32_t*)(smem_raw + OFF_BUF(b, 1) + r0 * ASTR + j0 * 2) = lo;
                        split2(s2, s3, hi, lo);
                        *(uint32_t*)(smem_raw + OFF_BUF(b, 0) + r1 * ASTR + j0 * 2) = hi;
                        *(uint32_t*)(smem_raw + OFF_BUF(b, 1) + r1 * ASTR + j0 * 2) = lo;
                    }
                }
                BARC();

                // ======== GEMM2: [32,128], k staged in 64-slices ========
                float d2[4][4];
                {
                    const int n0 = ng * 32;
                    #pragma unroll
                    for (int nt = 0; nt < 4; nt++) {
                        float bx = b2s[n0 + nt * 8 + jq];
                        float by = b2s[n0 + nt * 8 + jq + 1];
                        d2[nt][0] = bx; d2[nt][1] = by; d2[nt][2] = bx; d2[nt][3] = by;
                    }
                    const uint32_t* gw2h = (const uint32_t*)g_w2t_hi;
                    const uint32_t* gw2l = (const uint32_t*)g_w2t_lo;
                    #pragma unroll 1
                    for (int kt = 0; kt < 4; kt++) {
                        BARC();
                        #pragma unroll
                        for (int it2 = 0; it2 < 16; it2++) {
                            int idx = it2 * 256 + ctid;   // 4096 u32
                            int n = idx >> 5, ku = idx & 31;
                            swh[n * 36 + ku] = gw2h[n * 128 + kt * 32 + ku];
                            swl[n * 36 + ku] = gw2l[n * 128 + kt * 32 + ku];
                        }
                        BARC();
                        #pragma unroll
                        for (int sub = 0; sub < 4; sub++) {
                            uint32_t ah[4], al[4];
                            uint32_t aaddr = bufH + (m0 + (lane & 15)) * ASTR
                                + (kt * 64 + sub * 16 + ((lane >> 4) & 1) * 8) * 2;
                            ldm_x4(ah, aaddr);
                            ldm_x4(al, aaddr + BUF_SZ);
                            #pragma unroll
                            for (int nt = 0; nt < 4; nt++) {
                                uint32_t baddr = sb + OFF_WH
                                    + (n0 + nt * 8 + (lane & 7)) * 144
                                    + (sub * 16 + ((lane >> 3) & 1) * 8) * 2;
                                uint32_t bh[2], bl[2];
                                ldm_x2(bh, baddr);
                                ldm_x2(bl, baddr + (OFF_WL - OFF_WH));
                                mma_bf16(d2[nt], ah, bh);
                                mma_bf16(d2[nt], ah, bl);
                                mma_bf16(d2[nt], al, bh);
                            }
                        }
                    }
                }
                BARC();   // all h1 reads done

                // ---- epilogue2: fp32 D2 -> s_out (aliases bufL) ----
                {
                    float* so = (float*)(smem_raw + OFF_BUF(b, 1));   // [32][132]
                    const int n0 = ng * 32;
                    int r0 = m0 + (lane >> 2);
                    int r1 = r0 + 8;
                    #pragma unroll
                    for (int nt = 0; nt < 4; nt++) {
                        int j0 = n0 + nt * 8 + jq;
                        so[r0 * 132 + j0]     = d2[nt][0];
                        so[r0 * 132 + j0 + 1] = d2[nt][1];
                        so[r1 * 132 + j0]     = d2[nt][2];
                        so[r1 * 132 + j0 + 1] = d2[nt][3];
                    }
                }
                BARC();

                // ---- LayerNorm + residual: consumer warp cw -> rows cw*4..+3 ----
                {
                    const float* so = (const float*)(smem_raw + OFF_BUF(b, 1));
                    #pragma unroll 1
                    for (int rr = 0; rr < 4; rr++) {
                        int row  = cw * 4 + rr;
                        int node = node0 + row;
                        float v0 = so[row * 132 + lane];
                        float v1 = so[row * 132 + lane + 32];
                        float v2 = so[row * 132 + lane + 64];
                        float v3 = so[row * 132 + lane + 96];
                        float sum = v0 + v1 + v2 + v3;
                        float sq  = v0 * v0 + v1 * v1 + v2 * v2 + v3 * v3;
                        #pragma unroll
                        for (int o = 16; o > 0; o >>= 1) {
                            sum += __shfl_xor_sync(0xffffffffu, sum, o);
                            sq  += __shfl_xor_sync(0xffffffffu, sq,  o);
                        }
                        float mean = sum * (1.f / D);
                        float var  = sq * (1.f / D) - mean * mean;
                        float rstd = rsqrtf(var + LN_EPS);
                        if (node < N_NODES) {
                            long long base = (long long)node * D;
                            float g0 = gs[lane],      t0 = bts[lane];
                            float g1 = gs[lane + 32], t1 = bts[lane + 32];
                            float g2 = gs[lane + 64], t2 = bts[lane + 64];
                            float g3 = gs[lane + 96], t3 = bts[lane + 96];
                            out[base + lane]      = x[base + lane]      + (v0 - mean) * rstd * g0 + t0;
                            out[base + lane + 32] = x[base + lane + 32] + (v1 - mean) * rstd * g1 + t1;
                            out[base + lane + 64] = x[base + lane + 64] + (v2 - mean) * rstd * g2 + t2;
                            out[base + lane + 96] = x[base + lane + 96] + (v3 - mean) * rstd * g3 + t3;
                        }
                    }
                }
            }
        }
        __syncthreads();   // hand buffers across pipeline stages
    }
}

// ---------------------------------------------------------------------------
extern "C" void kernel_launch(void* const* d_in, const int* in_sizes, int n_in,
                              void* d_out, int out_size)
{
    const float* x          = (const float*)d_in[0];
    const void*  edge_index = d_in[1];
    const float* edge_attr  = (const float*)d_in[2];
    const float* W1         = (const float*)d_in[3];
    const float* b1         = (const float*)d_in[4];
    const float* W2         = (const float*)d_in[5];
    const float* b2         = (const float*)d_in[6];
    const float* gamma      = (const float*)d_in[7];
    const float* beta       = (const float*)d_in[8];
    float* out = (float*)d_out;

    cudaFuncSetAttribute(fused_kernel,
                         cudaFuncAttributeMaxDynamicSharedMemorySize, SMEM_TOT);

    zero_detect_prep_kernel<<<(2 * D * DHID + 255) / 256, 256>>>(edge_index, W1, W2);
    hist_kernel<<<(N_EDGES + 255) / 256, 256>>>(edge_index);
    bsum_kernel<<<NSB, SBLK>>>();
    offs_kernel<<<NSB, SBLK>>>();
    fill_kernel<<<(N_EDGES + 255) / 256, 256>>>(edge_index);

    fused_kernel<<<GRID, 512, SMEM_TOT>>>(
        x, edge_attr, b1, b2, gamma, beta, out);
}